// round 1
// baseline (speedup 1.0000x reference)
#include <cuda_runtime.h>
#include <cuda_bf16.h>
#include <mma.h>

using namespace nvcuda;

#define BB 4
#define NN 8192
#define IND 1024
#define HID 512
#define NHEAD 8
#define TOPK 16
#define NCLS 2
#define HH 91
#define PP (HH*HH)      // 8281
#define NP (PP+1)       // 8282 attention rows (cls + conv out)
#define MM (BB*NN)      // 32768

// ---------------- scratch (static __device__, no allocation) ----------------
__device__ __nv_bfloat16 g_in_bf[(size_t)MM*IND];   // 64 MB
__device__ __nv_bfloat16 g_W_bf[IND*HID];           // 1 MB
__device__ float g_venc[IND];
__device__ float g_scores[MM];
__device__ int   g_topk[BB*TOPK];
__device__ float g_suminp[BB*IND];
__device__ float g_Q[BB*HID];
__device__ float g_x[(size_t)MM*HID];               // relu(x - Q), 64 MB
__device__ float g_x2[(size_t)BB*NP*HID];           // cls + conv-out, 66 MB
__device__ float g_qvec[BB*HID];
__device__ float g_u[BB*NHEAD*HID];
__device__ float g_qbk[BB*NHEAD];
__device__ float g_logits[BB*NHEAD*NP];
__device__ float g_mx[BB*NHEAD];
__device__ float g_sm[BB*NHEAD];
__device__ float g_w[BB*NHEAD*HID];

// ---------------- v_enc = W_feat @ w_enc (fp32, exact scores path) ----------
__global__ void k_venc(const float* __restrict__ Wf, const float* __restrict__ wenc) {
    __shared__ float we[HID];
    int tid = threadIdx.x;
    for (int i = tid; i < HID; i += 256) we[i] = wenc[i];
    __syncthreads();
    int warp = tid >> 5, lane = tid & 31;
    int row = blockIdx.x * 8 + warp;
    const float4* r4 = (const float4*)(Wf + (size_t)row*HID);
    float acc = 0.f;
#pragma unroll
    for (int t = 0; t < 4; t++) {
        float4 f = r4[lane + t*32];
        int c = (lane + t*32)*4;
        acc += f.x*we[c] + f.y*we[c+1] + f.z*we[c+2] + f.w*we[c+3];
    }
    for (int o = 16; o; o >>= 1) acc += __shfl_xor_sync(0xffffffffu, acc, o);
    if (lane == 0) g_venc[row] = acc;
}

// ---------------- W_feat -> bf16 --------------------------------------------
__global__ void k_wbf(const float* __restrict__ Wf) {
    int i = blockIdx.x*blockDim.x + threadIdx.x;   // float4 index
    float4 f = ((const float4*)Wf)[i];
    __nv_bfloat162 lo = __floats2bfloat162_rn(f.x, f.y);
    __nv_bfloat162 hi = __floats2bfloat162_rn(f.z, f.w);
    uint2 u;
    u.x = *reinterpret_cast<unsigned*>(&lo);
    u.y = *reinterpret_cast<unsigned*>(&hi);
    ((uint2*)g_W_bf)[i] = u;
}

// ---------------- scores (fp32 GEMV) + inputs -> bf16, one pass -------------
__global__ void k_scores(const float* __restrict__ inp) {
    __shared__ float ve[IND];
    int tid = threadIdx.x;
    for (int i = tid; i < IND; i += 256) ve[i] = g_venc[i];
    __syncthreads();
    int warp = tid >> 5, lane = tid & 31;
    int row = blockIdx.x * 8 + warp;
    const float4* r4 = (const float4*)(inp + (size_t)row*IND);
    uint2* dst = (uint2*)(g_in_bf + (size_t)row*IND);
    float acc = 0.f;
#pragma unroll
    for (int t = 0; t < 8; t++) {
        int i = lane + t*32;
        float4 f = r4[i];
        int c = i*4;
        acc += f.x*ve[c] + f.y*ve[c+1] + f.z*ve[c+2] + f.w*ve[c+3];
        __nv_bfloat162 lo = __floats2bfloat162_rn(f.x, f.y);
        __nv_bfloat162 hi = __floats2bfloat162_rn(f.z, f.w);
        uint2 u;
        u.x = *reinterpret_cast<unsigned*>(&lo);
        u.y = *reinterpret_cast<unsigned*>(&hi);
        dst[i] = u;
    }
    for (int o = 16; o; o >>= 1) acc += __shfl_xor_sync(0xffffffffu, acc, o);
    if (lane == 0) g_scores[row] = acc;
}

// ---------------- top-16 per batch (iterated argmax, tie -> lower idx) ------
__global__ void k_topk() {
    __shared__ float sv[NN];
    __shared__ float rv[1024];
    __shared__ int   ri[1024];
    int b = blockIdx.x, tid = threadIdx.x;
    for (int i = tid; i < NN; i += 1024) sv[i] = g_scores[b*NN + i];
    __syncthreads();
    for (int k = 0; k < TOPK; k++) {
        float bv = -3.4e38f; int bi = 0x7fffffff;
        for (int i = tid; i < NN; i += 1024) {
            float v = sv[i];
            if (v > bv) { bv = v; bi = i; }
        }
        rv[tid] = bv; ri[tid] = bi;
        __syncthreads();
        for (int s = 512; s; s >>= 1) {
            if (tid < s) {
                if (rv[tid+s] > rv[tid] || (rv[tid+s] == rv[tid] && ri[tid+s] < ri[tid])) {
                    rv[tid] = rv[tid+s]; ri[tid] = ri[tid+s];
                }
            }
            __syncthreads();
        }
        if (tid == 0) { g_topk[b*TOPK + k] = ri[0]; sv[ri[0]] = -3.4e38f; }
        __syncthreads();
    }
}

// ---------------- sum of top-k input rows (fp32) ----------------------------
__global__ void k_suminp(const float* __restrict__ inp) {
    int b = blockIdx.x, tid = threadIdx.x;  // 1024 threads
    float acc = 0.f;
#pragma unroll
    for (int k = 0; k < TOPK; k++) {
        int r = g_topk[b*TOPK + k];
        acc += inp[((size_t)b*NN + r)*IND + tid];
    }
    g_suminp[b*IND + tid] = acc;
}

// ---------------- Q = suminp @ W_feat / 16 + b_feat (fp32 exact) ------------
__global__ void k_Q(const float* __restrict__ Wf, const float* __restrict__ bfeat) {
    __shared__ float s[IND];
    int b = blockIdx.x, tid = threadIdx.x;  // 512 threads
    for (int i = tid; i < IND; i += 512) s[i] = g_suminp[b*IND + i];
    __syncthreads();
    float acc = 0.f;
    for (int i = 0; i < IND; i++) acc += s[i]*Wf[(size_t)i*HID + tid];
    g_Q[b*HID + tid] = acc * (1.f/TOPK) + bfeat[tid];
}

// ---------------- main GEMM (bf16 wmma) + relu(x - Q) epilogue --------------
__global__ __launch_bounds__(256) void k_gemm(const float* __restrict__ bfeat) {
    __shared__ __align__(16) unsigned char raw[128*68*4];
    __nv_bfloat16 (*As)[72] = reinterpret_cast<__nv_bfloat16(*)[72]>(raw);
    __nv_bfloat16 (*Bs)[72] = reinterpret_cast<__nv_bfloat16(*)[72]>(raw + 128*72*2);
    float (*Es)[68] = reinterpret_cast<float(*)[68]>(raw);

    int tid = threadIdx.x;
    int m0 = blockIdx.y * 128;
    int n0 = blockIdx.x * 64;
    int b  = m0 >> 13;                 // /8192 (128 | 8192 so constant per block)
    int wid = tid >> 5;
    int wm = wid >> 1, wn = wid & 1;

    int cc = tid & 63;
    float qval = bfeat[n0 + cc] - g_Q[b*HID + n0 + cc];

    wmma::fragment<wmma::accumulator,16,16,16,float> c[2][2];
#pragma unroll
    for (int i = 0; i < 2; i++)
#pragma unroll
        for (int j = 0; j < 2; j++) wmma::fill_fragment(c[i][j], 0.f);

    for (int k0 = 0; k0 < IND; k0 += 64) {
        __syncthreads();
#pragma unroll
        for (int t = 0; t < 4; t++) {           // A tile: 128 x 64
            int idx = tid + t*256;
            int row = idx >> 3, v = idx & 7;
            *(float4*)&As[row][v*8] =
                ((const float4*)(g_in_bf + (size_t)(m0+row)*IND + k0))[v];
        }
#pragma unroll
        for (int t = 0; t < 2; t++) {           // B tile: 64 x 64
            int idx = tid + t*256;
            int row = idx >> 3, v = idx & 7;
            *(float4*)&Bs[row][v*8] =
                ((const float4*)(g_W_bf + (size_t)(k0+row)*HID + n0))[v];
        }
        __syncthreads();
#pragma unroll
        for (int kk = 0; kk < 64; kk += 16) {
            wmma::fragment<wmma::matrix_a,16,16,16,__nv_bfloat16,wmma::row_major> a0, a1;
            wmma::fragment<wmma::matrix_b,16,16,16,__nv_bfloat16,wmma::row_major> b0, b1;
            wmma::load_matrix_sync(a0, &As[wm*32][kk], 72);
            wmma::load_matrix_sync(a1, &As[wm*32+16][kk], 72);
            wmma::load_matrix_sync(b0, &Bs[kk][wn*32], 72);
            wmma::load_matrix_sync(b1, &Bs[kk][wn*32+16], 72);
            wmma::mma_sync(c[0][0], a0, b0, c[0][0]);
            wmma::mma_sync(c[0][1], a0, b1, c[0][1]);
            wmma::mma_sync(c[1][0], a1, b0, c[1][0]);
            wmma::mma_sync(c[1][1], a1, b1, c[1][1]);
        }
    }
    __syncthreads();
#pragma unroll
    for (int i = 0; i < 2; i++)
#pragma unroll
        for (int j = 0; j < 2; j++)
            wmma::store_matrix_sync(&Es[wm*32+i*16][wn*32+j*16], c[i][j], 68,
                                    wmma::mem_row_major);
    __syncthreads();
    int r0 = tid >> 6;
#pragma unroll
    for (int t = 0; t < 32; t++) {
        int r = r0 + t*4;
        g_x[(size_t)(m0 + r)*HID + n0 + cc] = fmaxf(Es[r][cc] + qval, 0.f);
    }
}

// ---------------- cls row ---------------------------------------------------
__global__ void k_cls(const float* __restrict__ cls) {
    g_x2[(size_t)blockIdx.x*NP*HID + threadIdx.x] = cls[threadIdx.x];
}

// ---------------- depthwise 3x3 conv (row-major, wrap rows, zero border) ----
__global__ void k_conv(const float* __restrict__ cw, const float* __restrict__ cb) {
    __shared__ float cws[HID*9];
    __shared__ float cbs[HID];
    int tid = threadIdx.x;   // 512 = channel
    int b = blockIdx.y;
#pragma unroll
    for (int k = 0; k < 9; k++) cws[tid*9 + k] = cw[tid*9 + k];
    cbs[tid] = cb[tid];
    __syncthreads();
    int p0 = blockIdx.x * 16;
    for (int i = 0; i < 16; i++) {
        int p = p0 + i;
        if (p >= PP) break;
        int y = p / HH, x = p - y*HH;
        float acc = 0.f, center = 0.f;
#pragma unroll
        for (int dy = -1; dy <= 1; dy++) {
            int yy = y + dy; if (yy < 0 || yy >= HH) continue;
#pragma unroll
            for (int dx = -1; dx <= 1; dx++) {
                int xx = x + dx; if (xx < 0 || xx >= HH) continue;
                int pp2 = yy*HH + xx;
                int r = (pp2 < NN) ? pp2 : pp2 - NN;   // wrap padding rows
                float v = g_x[((size_t)(b*NN + r))*HID + tid];
                acc += v * cws[tid*9 + (dy+1)*3 + (dx+1)];
                if (dy == 0 && dx == 0) center = v;
            }
        }
        g_x2[((size_t)b*NP + 1 + p)*HID + tid] = acc + cbs[tid] + center;
    }
}

// ---------------- q projection + per-head key vectors u ---------------------
__global__ void k_attnprep(const float* __restrict__ Wq, const float* __restrict__ bq,
                           const float* __restrict__ Wk, const float* __restrict__ bk) {
    __shared__ float qs[HID];
    int b = blockIdx.x, tid = threadIdx.x;  // 512
    qs[tid] = g_Q[b*HID + tid];
    __syncthreads();
    float acc = bq[tid];
    for (int c = 0; c < HID; c++) acc += qs[c]*Wq[(size_t)c*HID + tid];
    __syncthreads();
    qs[tid] = acc;
    g_qvec[b*HID + tid] = acc;
    __syncthreads();
#pragma unroll
    for (int h = 0; h < NHEAD; h++) {
        float u = 0.f;
        const float* wr = Wk + (size_t)tid*HID + h*64;
        const float* qh = qs + h*64;
        for (int d = 0; d < 64; d++) u += wr[d]*qh[d];
        g_u[(b*NHEAD + h)*HID + tid] = u;
    }
    if (tid < NHEAD) {
        float qb = 0.f;
        for (int d = 0; d < 64; d++) qb += bk[tid*64 + d]*qs[tid*64 + d];
        g_qbk[b*NHEAD + tid] = qb;
    }
    for (int t = tid; t < NHEAD*HID; t += 512) g_w[b*NHEAD*HID + t] = 0.f;
}

// ---------------- logits over 8282 keys (8 heads per row pass) --------------
__global__ void k_logits() {
    __shared__ float us[NHEAD*HID];
    __shared__ float qb[NHEAD];
    int tid = threadIdx.x;  // 256
    int b = blockIdx.y;
    for (int i = tid; i < NHEAD*HID; i += 256) us[i] = g_u[b*NHEAD*HID + i];
    if (tid < NHEAD) qb[tid] = g_qbk[b*NHEAD + tid];
    __syncthreads();
    int warp = tid >> 5, lane = tid & 31;
    const float RS = 0.0441941738241592f;   // 1/sqrt(512)
    for (int it = 0; it < 4; it++) {
        int n = blockIdx.x*32 + warp*4 + it;
        if (n >= NP) break;
        const float4* row = (const float4*)(g_x2 + ((size_t)b*NP + n)*HID);
        float acc[NHEAD] = {0,0,0,0,0,0,0,0};
#pragma unroll
        for (int t = 0; t < 4; t++) {
            float4 f = row[lane + t*32];
            int c = (lane + t*32)*4;
#pragma unroll
            for (int h = 0; h < NHEAD; h++) {
                const float* uh = us + h*HID + c;
                acc[h] += f.x*uh[0] + f.y*uh[1] + f.z*uh[2] + f.w*uh[3];
            }
        }
#pragma unroll
        for (int h = 0; h < NHEAD; h++)
            for (int o = 16; o; o >>= 1) acc[h] += __shfl_xor_sync(0xffffffffu, acc[h], o);
        if (lane == 0) {
#pragma unroll
            for (int h = 0; h < NHEAD; h++)
                g_logits[((size_t)(b*NHEAD + h))*NP + n] = (acc[h] + qb[h]) * RS;
        }
    }
}

// ---------------- softmax stats (max, sumexp) per (b,h) ---------------------
__global__ void k_softmax() {
    __shared__ float red[256];
    int bh = blockIdx.x, tid = threadIdx.x;
    const float* l = g_logits + (size_t)bh*NP;
    float m = -3.4e38f;
    for (int i = tid; i < NP; i += 256) m = fmaxf(m, l[i]);
    red[tid] = m; __syncthreads();
    for (int s = 128; s; s >>= 1) { if (tid < s) red[tid] = fmaxf(red[tid], red[tid+s]); __syncthreads(); }
    m = red[0]; __syncthreads();
    float sum = 0.f;
    for (int i = tid; i < NP; i += 256) sum += expf(l[i] - m);
    red[tid] = sum; __syncthreads();
    for (int s = 128; s; s >>= 1) { if (tid < s) red[tid] += red[tid+s]; __syncthreads(); }
    if (tid == 0) { g_mx[bh] = m; g_sm[bh] = red[0]; }
}

// ---------------- weighted sums w[b,h,:] = sum_n A x2[n,:] ------------------
#define WCH 130
__global__ void k_wsum() {
    __shared__ float as[NHEAD*WCH];
    int tid = threadIdx.x;   // 512 = channel
    int b = blockIdx.y;
    int base = blockIdx.x * WCH;
    for (int idx = tid; idx < NHEAD*WCH; idx += 512) {
        int h = idx / WCH, i = idx - h*WCH;
        int n = base + i;
        float a = 0.f;
        if (n < NP) {
            int bh = b*NHEAD + h;
            a = expf(g_logits[(size_t)bh*NP + n] - g_mx[bh]) / g_sm[bh];
        }
        as[idx] = a;
    }
    __syncthreads();
    float w[NHEAD] = {0,0,0,0,0,0,0,0};
    for (int i = 0; i < WCH; i++) {
        int n = base + i;
        if (n >= NP) break;
        float v = g_x2[((size_t)b*NP + n)*HID + tid];
#pragma unroll
        for (int h = 0; h < NHEAD; h++) w[h] += as[h*WCH + i]*v;
    }
#pragma unroll
    for (int h = 0; h < NHEAD; h++)
        atomicAdd(&g_w[(b*NHEAD + h)*HID + tid], w[h]);
}

// ---------------- finale: O = q + w@Wv + bv; O += relu(O@Wo+bo); out=O@Wc+bc
__global__ void k_finale(const float* __restrict__ Wv, const float* __restrict__ bv,
                         const float* __restrict__ Wo, const float* __restrict__ bo,
                         const float* __restrict__ Wc, const float* __restrict__ bc,
                         float* __restrict__ out) {
    __shared__ float ws[NHEAD*HID];
    __shared__ float Ov[HID];
    __shared__ float red[HID];
    int b = blockIdx.x, tid = threadIdx.x;  // 512
    for (int i = tid; i < NHEAD*HID; i += 512) ws[i] = g_w[b*NHEAD*HID + i];
    __syncthreads();
    int h = tid >> 6;
    float acc = bv[tid] + g_qvec[b*HID + tid];
    const float* wh = ws + h*HID;
    for (int c = 0; c < HID; c++) acc += wh[c]*Wv[(size_t)c*HID + tid];
    Ov[tid] = acc;
    __syncthreads();
    float t2 = bo[tid];
    for (int c = 0; c < HID; c++) t2 += Ov[c]*Wo[(size_t)c*HID + tid];
    __syncthreads();
    Ov[tid] = Ov[tid] + fmaxf(t2, 0.f);
    __syncthreads();
    for (int j = 0; j < NCLS; j++) {
        red[tid] = Ov[tid]*Wc[tid*NCLS + j];
        __syncthreads();
        for (int s = 256; s; s >>= 1) { if (tid < s) red[tid] += red[tid+s]; __syncthreads(); }
        if (tid == 0) out[b*NCLS + j] = red[0] + bc[j];
        __syncthreads();
    }
}

// ---------------------------------------------------------------------------
extern "C" void kernel_launch(void* const* d_in, const int* in_sizes, int n_in,
                              void* d_out, int out_size) {
    const float* inputs  = (const float*)d_in[0];
    const float* W_feat  = (const float*)d_in[1];
    const float* b_feat  = (const float*)d_in[2];
    const float* w_enc   = (const float*)d_in[3];
    // d_in[4] = b_enc: uniform shift before sigmoid -> does not affect top-k
    const float* cls_tok = (const float*)d_in[5];
    const float* conv_w  = (const float*)d_in[6];
    const float* conv_b  = (const float*)d_in[7];
    const float* Wq = (const float*)d_in[8];
    const float* bq = (const float*)d_in[9];
    const float* Wk = (const float*)d_in[10];
    const float* bk = (const float*)d_in[11];
    const float* Wv = (const float*)d_in[12];
    const float* bv = (const float*)d_in[13];
    const float* Wo = (const float*)d_in[14];
    const float* bo = (const float*)d_in[15];
    const float* Wc = (const float*)d_in[16];
    const float* bc = (const float*)d_in[17];
    float* out = (float*)d_out;

    k_venc  <<<128, 256>>>(W_feat, w_enc);
    k_wbf   <<<IND*HID/4/256, 256>>>(W_feat);
    k_scores<<<MM/8, 256>>>(inputs);
    k_topk  <<<BB, 1024>>>();
    k_suminp<<<BB, 1024>>>(inputs);
    k_Q     <<<BB, 512>>>(W_feat, b_feat);
    k_gemm  <<<dim3(HID/64, MM/128), 256>>>(b_feat);
    k_cls   <<<BB, 512>>>(cls_tok);
    k_conv  <<<dim3((PP+15)/16, BB), 512>>>(conv_w, conv_b);
    k_attnprep<<<BB, 512>>>(Wq, bq, Wk, bk);
    k_logits<<<dim3((NP+31)/32, BB), 256>>>();
    k_softmax<<<BB*NHEAD, 256>>>();
    k_wsum  <<<dim3((NP+WCH-1)/WCH, BB), 512>>>();
    k_finale<<<BB, 512>>>(Wv, bv, Wo, bo, Wc, bc, out);
}